// round 4
// baseline (speedup 1.0000x reference)
#include <cuda_runtime.h>
#include <math.h>
#include <stdint.h>

#define BB 4
#define TT 128
#define HH 1024
#define NN 300
#define VV 50265
#define EE 4800
#define BT (BB*TT)      // 512
#define KK2 (2*HH)      // 2048

// ---------------- scratch (device globals; no allocations) ----------------
__device__ __align__(16) float g_hq[BT*KK2];      // concat(hidden, qt), tf32-rounded
__device__ float g_vh[HH], g_vs[HH], g_vx[HH];
__device__ float g_ps[BT], g_gg[BT], g_mg[BT];
__device__ float g_cp[BT*NN];
__device__ float g_graphT[BB*NN*NN];
__device__ float g_M[BT*NN];
__device__ float g_pg[BT*NN];

__device__ __forceinline__ uint32_t f2tf32(float f) {
    uint32_t r;
    asm("cvt.rna.tf32.f32 %0, %1;" : "=r"(r) : "f"(f));
    return r;
}

// ---------------- reductions ----------------
__device__ __forceinline__ float blk_reduce_sum(float v, float* sh) {
    int lane = threadIdx.x & 31, w = threadIdx.x >> 5;
    #pragma unroll
    for (int d = 16; d; d >>= 1) v += __shfl_down_sync(0xffffffffu, v, d);
    if (lane == 0) sh[w] = v;
    __syncthreads();
    int nw = (blockDim.x + 31) >> 5;
    if (threadIdx.x < 32) {
        float r = (lane < nw) ? sh[lane] : 0.f;
        #pragma unroll
        for (int d = 16; d; d >>= 1) r += __shfl_down_sync(0xffffffffu, r, d);
        if (lane == 0) sh[0] = r;
    }
    __syncthreads();
    return sh[0];
}

__device__ __forceinline__ float blk_reduce_max(float v, float* sh) {
    int lane = threadIdx.x & 31, w = threadIdx.x >> 5;
    #pragma unroll
    for (int d = 16; d; d >>= 1) v = fmaxf(v, __shfl_down_sync(0xffffffffu, v, d));
    if (lane == 0) sh[w] = v;
    __syncthreads();
    int nw = (blockDim.x + 31) >> 5;
    if (threadIdx.x < 32) {
        float r = (lane < nw) ? sh[lane] : -1e30f;
        #pragma unroll
        for (int d = 16; d; d >>= 1) r = fmaxf(r, __shfl_down_sync(0xffffffffu, r, d));
        if (lane == 0) sh[0] = r;
    }
    __syncthreads();
    return sh[0];
}

// ---------------- small kernels ----------------

__global__ void k_zero(float* out_cov) {
    int i = blockIdx.x * blockDim.x + threadIdx.x;
    if (i < BB*NN*NN) g_graphT[i] = 0.f;
    if (i < BB*NN)    out_cov[i]  = 0.f;
}

__global__ void k_vec(const float* __restrict__ Wh, const float* __restrict__ Ws,
                      const float* __restrict__ Wx, const float* __restrict__ Wps) {
    int gw   = (blockIdx.x * blockDim.x + threadIdx.x) >> 5;
    int lane = threadIdx.x & 31;
    if (gw >= 3 * HH) return;
    int mat = gw >> 10, row = gw & (HH - 1);
    const float* W = (mat == 0) ? Wh : (mat == 1) ? Ws : Wx;
    float s = 0.f;
    for (int o = lane; o < HH; o += 32) s += W[row * HH + o] * Wps[o];
    #pragma unroll
    for (int d = 16; d; d >>= 1) s += __shfl_down_sync(0xffffffffu, s, d);
    if (lane == 0) ((mat == 0) ? g_vh : (mat == 1) ? g_vs : g_vx)[row] = s;
}

__global__ void k_tok(const float* __restrict__ hs, const float* __restrict__ qt,
                      const float* __restrict__ te,
                      const float* __restrict__ bx, const float* __restrict__ Wps,
                      const float* __restrict__ bps,
                      const float* __restrict__ Wgg, const float* __restrict__ bgg,
                      const float* __restrict__ Wmg, const float* __restrict__ bmg,
                      float* out_ps) {
    int tok = blockIdx.x;
    int tid = threadIdx.x;
    const float* h = hs + (size_t)tok * HH;
    const float* q = qt + (size_t)tok * HH;
    const float* e = te + (size_t)tok * HH;
    float sp = 0.f, sg = 0.f, sm = 0.f;
    for (int k = tid; k < HH; k += blockDim.x) {
        float hv = h[k], qv = q[k], ev = e[k];
        // pre-round to tf32 so the GEMM A-fragments need no in-loop cvt
        g_hq[(size_t)tok * KK2 + k]      = __uint_as_float(f2tf32(hv));
        g_hq[(size_t)tok * KK2 + HH + k] = __uint_as_float(f2tf32(qv));
        sp += hv * g_vh[k] + qv * g_vs[k] + ev * g_vx[k] + bx[k] * Wps[k];
        sg += hv * Wgg[k] + qv * Wgg[HH + k];
        sm += hv * Wmg[k] + qv * Wmg[HH + k];
    }
    __shared__ float sh0[32], sh1[32], sh2[32];
    sp = blk_reduce_sum(sp, sh0);
    sg = blk_reduce_sum(sg, sh1);
    sm = blk_reduce_sum(sm, sh2);
    if (tid == 0) {
        float ps = 1.f / (1.f + expf(-(sp + bps[0])));
        float gg = 1.f / (1.f + expf(-(sg + bgg[0])));
        float mg = 1.f / (1.f + expf(-(sm + bmg[0])));
        g_ps[tok] = ps; g_gg[tok] = gg; g_mg[tok] = mg;
        out_ps[tok] = ps;
    }
}

__global__ void k_edges(const int* __restrict__ edges) {
    int i = blockIdx.x * blockDim.x + threadIdx.x;
    if (i >= BB * EE) return;
    int b = i / EE, e = i % EE;
    int src = edges[b * 2 * EE + e];
    int dst = edges[b * 2 * EE + EE + e];
    atomicAdd(&g_graphT[b * NN * NN + dst * NN + src], 1.0f);
}

#define CP_TOK 4
__global__ void k_cp(const float* __restrict__ qt, const float* __restrict__ te,
                     const float* __restrict__ Wc, const float* __restrict__ bc) {
    __shared__ float qe[CP_TOK][KK2];
    int t0 = blockIdx.x * CP_TOK;
    int tid = threadIdx.x;
    for (int idx = tid; idx < CP_TOK * KK2; idx += blockDim.x) {
        int tt = idx / KK2, k = idx % KK2;
        qe[tt][k] = (k < HH) ? qt[(size_t)(t0 + tt) * HH + k]
                             : te[(size_t)(t0 + tt) * HH + k - HH];
    }
    __syncthreads();
    int n = tid;
    if (n >= NN) return;
    float acc[CP_TOK];
    #pragma unroll
    for (int tt = 0; tt < CP_TOK; tt++) acc[tt] = bc[n];
    for (int k = 0; k < KK2; k++) {
        float w = Wc[(size_t)k * NN + n];
        #pragma unroll
        for (int tt = 0; tt < CP_TOK; tt++) acc[tt] = fmaf(qe[tt][k], w, acc[tt]);
    }
    #pragma unroll
    for (int tt = 0; tt < CP_TOK; tt++) g_cp[(size_t)(t0 + tt) * NN + n] = acc[tt];
}

__global__ void k_m() {
    int b = blockIdx.x, n = threadIdx.x;
    if (n >= NN) return;
    float m = 0.f;
    for (int t = 0; t < TT; t++) {
        int bt = b * TT + t;
        float mg = g_mg[bt];
        m = g_cp[(size_t)bt * NN + n] * mg + m * (1.f - mg);
        g_M[(size_t)bt * NN + n] = m;
    }
}

#define GS_TT 16
__global__ void k_gsem() {
    __shared__ float Msh[GS_TT * NN];
    int b = blockIdx.x, t0 = blockIdx.y * GS_TT;
    int tid = threadIdx.x;
    for (int idx = tid; idx < GS_TT * NN; idx += blockDim.x) {
        int tt = idx / NN, j = idx % NN;
        Msh[tt * NN + j] = g_M[(size_t)(b * TT + t0 + tt) * NN + j];
    }
    __syncthreads();
    int i = tid;
    if (i >= NN) return;
    float acc[GS_TT];
    #pragma unroll
    for (int tt = 0; tt < GS_TT; tt++) acc[tt] = 0.f;
    const float* GT = g_graphT + (size_t)b * NN * NN;
    for (int j = 0; j < NN; j++) {
        float g = GT[(size_t)j * NN + i];
        #pragma unroll
        for (int tt = 0; tt < GS_TT; tt++) acc[tt] = fmaf(g, Msh[tt * NN + j], acc[tt]);
    }
    #pragma unroll
    for (int tt = 0; tt < GS_TT; tt++) {
        int bt = b * TT + t0 + tt;
        float gg = g_gg[bt];
        g_pg[(size_t)bt * NN + i] = g_cp[(size_t)bt * NN + i] * gg + acc[tt] * (1.f - gg);
    }
}

__global__ void k_cov(float* out_cov) {
    int bt = blockIdx.x;
    int b = bt / TT;
    int tid = threadIdx.x;
    float ps = g_ps[bt];
    float x = (tid < NN) ? g_pg[(size_t)bt * NN + tid] * ps : -1e30f;
    __shared__ float shm[32], shs[32];
    float mx = blk_reduce_max(x, shm);
    float e = (tid < NN) ? expf(x - mx) : 0.f;
    float s = blk_reduce_sum(e, shs);
    if (tid < NN) atomicAdd(&out_cov[b * NN + tid], e / s);
}

__global__ void k_scatter(const int* __restrict__ nidx, float* __restrict__ out) {
    int i = blockIdx.x * blockDim.x + threadIdx.x;
    if (i >= BT * NN) return;
    int bt = i / NN, n = i % NN;
    atomicAdd(&out[(size_t)bt * VV + nidx[n]], g_pg[i] * g_ps[bt]);
}

// ================= tf32 mma.sync GEMM =================
// out[m,n] = (hq @ Wg + bg) * (1 - ps),  M=512, K=2048, N=50265
// BM=128 BN=128 BK=32, 256 thr, warp = 64x32 (4x4 m16n8k8), cp.async dbl-buffer.

#define GM_BM 128
#define GM_BN 128
#define GM_BK 32
#define GM_KB (KK2 / GM_BK)        // 64
#define GM_PA 36                   // As pitch (floats): bank = (4m + k) % 32
#define GM_PB 136                  // Bs pitch (floats): bank = (8k + n) % 32
#define GM_ASZ (GM_BM * GM_PA)     // 4608 floats
#define GM_BSZ (GM_BK * GM_PB)     // 4352 floats
#define GM_STG (GM_ASZ + GM_BSZ)   // 8960 floats per stage
#define GM_SMEM (2 * GM_STG * 4)   // 71680 bytes

__device__ __forceinline__ uint32_t smem_u32(const void* p) {
    uint32_t a;
    asm("{ .reg .u64 t; cvta.to.shared.u64 t, %1; cvt.u32.u64 %0, t; }" : "=r"(a) : "l"(p));
    return a;
}
__device__ __forceinline__ void cp16(uint32_t dst, const float* src) {
    asm volatile("cp.async.cg.shared.global [%0], [%1], 16;" :: "r"(dst), "l"(src));
}
__device__ __forceinline__ void cp4z(uint32_t dst, const float* src, bool ok) {
    int sz = ok ? 4 : 0;
    asm volatile("cp.async.ca.shared.global [%0], [%1], 4, %2;" :: "r"(dst), "l"(src), "r"(sz));
}

#define MMA_TF32(c, a, b) \
    asm volatile("mma.sync.aligned.m16n8k8.row.col.f32.tf32.tf32.f32 " \
        "{%0,%1,%2,%3}, {%4,%5,%6,%7}, {%8,%9}, {%0,%1,%2,%3};" \
        : "+f"((c)[0]), "+f"((c)[1]), "+f"((c)[2]), "+f"((c)[3]) \
        : "r"((a)[0]), "r"((a)[1]), "r"((a)[2]), "r"((a)[3]), "r"((b)[0]), "r"((b)[1]))

__global__ __launch_bounds__(256)
void k_gemm_mma(const float* __restrict__ Wg, const float* __restrict__ bg,
                float* __restrict__ out) {
    extern __shared__ float smf[];
    const int tid = threadIdx.x;
    const int lane = tid & 31, wid = tid >> 5;
    const int m0 = blockIdx.x * GM_BM;      // x = m (fastest) for Wg L2 reuse
    const int n0 = blockIdx.y * GM_BN;
    const int wm = (wid & 1) * 64, wn = (wid >> 1) * 32;
    const int r = lane >> 2, c = lane & 3;
    const uint32_t sbase = smem_u32(smf);

    float acc[4][4][4];
    #pragma unroll
    for (int mi = 0; mi < 4; mi++)
        #pragma unroll
        for (int nj = 0; nj < 4; nj++)
            #pragma unroll
            for (int q = 0; q < 4; q++) acc[mi][nj][q] = 0.f;

    // ---- async stage loader ----
    auto load_stage = [&](int kb, int buf) {
        const int k0 = kb * GM_BK;
        const uint32_t sA = sbase + (uint32_t)(buf * GM_STG) * 4u;
        const uint32_t sB = sA + (uint32_t)GM_ASZ * 4u;
        // A: 128m x 32k, 16B chunks, dst As[m][k] pitch 36 (conflict-free)
        #pragma unroll
        for (int i = 0; i < 4; i++) {
            int idx = i * 256 + tid;            // 0..1023
            int m = idx >> 3, kc = (idx & 7) * 4;
            cp16(sA + (uint32_t)(m * GM_PA + kc) * 4u,
                 &g_hq[(size_t)(m0 + m) * KK2 + k0 + kc]);
        }
        // B: 32k x 128n, 4B (Wg rows only 4B-aligned), dst Bs[k][n] pitch 136
        #pragma unroll
        for (int i = 0; i < 16; i++) {
            int idx = i * 256 + tid;            // 0..4095
            int k = idx >> 7, n = idx & 127;
            bool ok = (n0 + n) < VV;
            const float* src = ok ? (Wg + (size_t)(k0 + k) * VV + (n0 + n)) : Wg;
            cp4z(sB + (uint32_t)(k * GM_PB + n) * 4u, src, ok);
        }
        asm volatile("cp.async.commit_group;" ::: "memory");
    };

    load_stage(0, 0);

    #pragma unroll 1
    for (int kb = 0; kb < GM_KB; kb++) {
        const int buf = kb & 1;
        if (kb + 1 < GM_KB) {
            load_stage(kb + 1, buf ^ 1);
            asm volatile("cp.async.wait_group 1;" ::: "memory");
        } else {
            asm volatile("cp.async.wait_group 0;" ::: "memory");
        }
        __syncthreads();

        const float* As = smf + buf * GM_STG;
        const float* Bs = As + GM_ASZ;
        #pragma unroll
        for (int ks = 0; ks < 4; ks++) {
            uint32_t a[4][4], b[4][2];
            #pragma unroll
            for (int mi = 0; mi < 4; mi++) {
                int m = wm + mi * 16 + r;
                int kk = ks * 8 + c;
                a[mi][0] = __float_as_uint(As[m * GM_PA + kk]);
                a[mi][1] = __float_as_uint(As[(m + 8) * GM_PA + kk]);
                a[mi][2] = __float_as_uint(As[m * GM_PA + kk + 4]);
                a[mi][3] = __float_as_uint(As[(m + 8) * GM_PA + kk + 4]);
            }
            #pragma unroll
            for (int nj = 0; nj < 4; nj++) {
                int n = wn + nj * 8 + r;
                int kk = ks * 8 + c;
                b[nj][0] = f2tf32(Bs[kk * GM_PB + n]);
                b[nj][1] = f2tf32(Bs[(kk + 4) * GM_PB + n]);
            }
            #pragma unroll
            for (int mi = 0; mi < 4; mi++)
                #pragma unroll
                for (int nj = 0; nj < 4; nj++)
                    MMA_TF32(acc[mi][nj], a[mi], b[nj]);
        }
        __syncthreads();
    }

    // ---- epilogue: out = (acc + bg) * (1 - ps) ----
    #pragma unroll
    for (int mi = 0; mi < 4; mi++) {
        int mA = m0 + wm + mi * 16 + r;
        int mB = mA + 8;
        float sA = 1.f - g_ps[mA];
        float sB = 1.f - g_ps[mB];
        #pragma unroll
        for (int nj = 0; nj < 4; nj++) {
            int n = n0 + wn + nj * 8 + c * 2;
            if (n < VV) {
                float bgv = bg[n];
                out[(size_t)mA * VV + n] = (acc[mi][nj][0] + bgv) * sA;
                out[(size_t)mB * VV + n] = (acc[mi][nj][2] + bgv) * sB;
            }
            if (n + 1 < VV) {
                float bgv = bg[n + 1];
                out[(size_t)mA * VV + n + 1] = (acc[mi][nj][1] + bgv) * sA;
                out[(size_t)mB * VV + n + 1] = (acc[mi][nj][3] + bgv) * sB;
            }
        }
    }
}

// ---------------- launch ----------------
extern "C" void kernel_launch(void* const* d_in, const int* in_sizes, int n_in,
                              void* d_out, int out_size) {
    const float* hs   = (const float*)d_in[0];
    const float* qt   = (const float*)d_in[1];
    const float* te   = (const float*)d_in[2];
    const int*   edges= (const int*)  d_in[3];
    const int*   nidx = (const int*)  d_in[4];
    const float* Wg   = (const float*)d_in[5];
    const float* bg   = (const float*)d_in[6];
    const float* Wh   = (const float*)d_in[7];
    const float* Ws   = (const float*)d_in[8];
    const float* Wx   = (const float*)d_in[9];
    const float* bx   = (const float*)d_in[10];
    const float* Wps  = (const float*)d_in[11];
    const float* bps  = (const float*)d_in[12];
    const float* Wc   = (const float*)d_in[13];
    const float* bc   = (const float*)d_in[14];
    const float* Wgg  = (const float*)d_in[15];
    const float* bgg  = (const float*)d_in[16];
    const float* Wmg  = (const float*)d_in[17];
    const float* bmg  = (const float*)d_in[18];

    float* out    = (float*)d_out;
    float* outCov = out + (size_t)BT * VV;
    float* outPs  = outCov + BB * NN;

    cudaFuncSetAttribute(k_gemm_mma, cudaFuncAttributeMaxDynamicSharedMemorySize, GM_SMEM);

    k_zero<<<(BB*NN*NN + 255) / 256, 256>>>(outCov);
    k_vec<<<(3 * HH * 32 + 255) / 256, 256>>>(Wh, Ws, Wx, Wps);
    k_tok<<<BT, 256>>>(hs, qt, te, bx, Wps, bps, Wgg, bgg, Wmg, bmg, outPs);
    k_edges<<<(BB*EE + 255) / 256, 256>>>(edges);
    k_cp<<<BT / CP_TOK, 320>>>(qt, te, Wc, bc);
    k_m<<<BB, 320>>>();
    k_gsem<<<dim3(BB, TT / GS_TT), 320>>>();
    k_cov<<<BT, 320>>>(outCov);
    k_gemm_mma<<<dim3(BT / GM_BM, (VV + GM_BN - 1) / GM_BN), 256, GM_SMEM>>>(Wg, bg, out);
    k_scatter<<<(BT*NN + 255) / 256, 256>>>(nidx, out);
}

// round 5
// speedup vs baseline: 1.1807x; 1.1807x over previous
#include <cuda_runtime.h>
#include <cuda_fp16.h>
#include <math.h>
#include <stdint.h>

#define BB 4
#define TT 128
#define HH 1024
#define NN 300
#define VV 50265
#define EE 4800
#define BT (BB*TT)      // 512
#define KK2 (2*HH)      // 2048

// ---------------- scratch (device globals; no allocations) ----------------
__device__ __align__(16) __half g_hqH[BT*KK2];    // concat(hidden, qt) fp16 [512,2048]
__device__ float g_vh[HH], g_vs[HH], g_vx[HH];
__device__ float g_ps[BT], g_gg[BT], g_mg[BT];
__device__ float g_cp[BT*NN];
__device__ float g_graphT[BB*NN*NN];
__device__ float g_M[BT*NN];
__device__ float g_pg[BT*NN];

// ---------------- reductions ----------------
__device__ __forceinline__ float blk_reduce_sum(float v, float* sh) {
    int lane = threadIdx.x & 31, w = threadIdx.x >> 5;
    #pragma unroll
    for (int d = 16; d; d >>= 1) v += __shfl_down_sync(0xffffffffu, v, d);
    if (lane == 0) sh[w] = v;
    __syncthreads();
    int nw = (blockDim.x + 31) >> 5;
    if (threadIdx.x < 32) {
        float r = (lane < nw) ? sh[lane] : 0.f;
        #pragma unroll
        for (int d = 16; d; d >>= 1) r += __shfl_down_sync(0xffffffffu, r, d);
        if (lane == 0) sh[0] = r;
    }
    __syncthreads();
    return sh[0];
}

__device__ __forceinline__ float blk_reduce_max(float v, float* sh) {
    int lane = threadIdx.x & 31, w = threadIdx.x >> 5;
    #pragma unroll
    for (int d = 16; d; d >>= 1) v = fmaxf(v, __shfl_down_sync(0xffffffffu, v, d));
    if (lane == 0) sh[w] = v;
    __syncthreads();
    int nw = (blockDim.x + 31) >> 5;
    if (threadIdx.x < 32) {
        float r = (lane < nw) ? sh[lane] : -1e30f;
        #pragma unroll
        for (int d = 16; d; d >>= 1) r = fmaxf(r, __shfl_down_sync(0xffffffffu, r, d));
        if (lane == 0) sh[0] = r;
    }
    __syncthreads();
    return sh[0];
}

// ---------------- small kernels ----------------

__global__ void k_zero(float* out_cov) {
    int i = blockIdx.x * blockDim.x + threadIdx.x;
    if (i < BB*NN*NN) g_graphT[i] = 0.f;
    if (i < BB*NN)    out_cov[i]  = 0.f;
}

__global__ void k_vec(const float* __restrict__ Wh, const float* __restrict__ Ws,
                      const float* __restrict__ Wx, const float* __restrict__ Wps) {
    int gw   = (blockIdx.x * blockDim.x + threadIdx.x) >> 5;
    int lane = threadIdx.x & 31;
    if (gw >= 3 * HH) return;
    int mat = gw >> 10, row = gw & (HH - 1);
    const float* W = (mat == 0) ? Wh : (mat == 1) ? Ws : Wx;
    float s = 0.f;
    for (int o = lane; o < HH; o += 32) s += W[row * HH + o] * Wps[o];
    #pragma unroll
    for (int d = 16; d; d >>= 1) s += __shfl_down_sync(0xffffffffu, s, d);
    if (lane == 0) ((mat == 0) ? g_vh : (mat == 1) ? g_vs : g_vx)[row] = s;
}

__global__ void k_tok(const float* __restrict__ hs, const float* __restrict__ qt,
                      const float* __restrict__ te,
                      const float* __restrict__ bx, const float* __restrict__ Wps,
                      const float* __restrict__ bps,
                      const float* __restrict__ Wgg, const float* __restrict__ bgg,
                      const float* __restrict__ Wmg, const float* __restrict__ bmg,
                      float* out_ps) {
    int tok = blockIdx.x;
    int tid = threadIdx.x;
    const float* h = hs + (size_t)tok * HH;
    const float* q = qt + (size_t)tok * HH;
    const float* e = te + (size_t)tok * HH;
    float sp = 0.f, sg = 0.f, sm = 0.f;
    for (int k = tid; k < HH; k += blockDim.x) {
        float hv = h[k], qv = q[k], ev = e[k];
        g_hqH[(size_t)tok * KK2 + k]      = __float2half_rn(hv);
        g_hqH[(size_t)tok * KK2 + HH + k] = __float2half_rn(qv);
        sp += hv * g_vh[k] + qv * g_vs[k] + ev * g_vx[k] + bx[k] * Wps[k];
        sg += hv * Wgg[k] + qv * Wgg[HH + k];
        sm += hv * Wmg[k] + qv * Wmg[HH + k];
    }
    __shared__ float sh0[32], sh1[32], sh2[32];
    sp = blk_reduce_sum(sp, sh0);
    sg = blk_reduce_sum(sg, sh1);
    sm = blk_reduce_sum(sm, sh2);
    if (tid == 0) {
        float ps = 1.f / (1.f + expf(-(sp + bps[0])));
        float gg = 1.f / (1.f + expf(-(sg + bgg[0])));
        float mg = 1.f / (1.f + expf(-(sm + bmg[0])));
        g_ps[tok] = ps; g_gg[tok] = gg; g_mg[tok] = mg;
        out_ps[tok] = ps;
    }
}

__global__ void k_edges(const int* __restrict__ edges) {
    int i = blockIdx.x * blockDim.x + threadIdx.x;
    if (i >= BB * EE) return;
    int b = i / EE, e = i % EE;
    int src = edges[b * 2 * EE + e];
    int dst = edges[b * 2 * EE + EE + e];
    atomicAdd(&g_graphT[b * NN * NN + dst * NN + src], 1.0f);
}

#define CP_TOK 4
__global__ void k_cp(const float* __restrict__ qt, const float* __restrict__ te,
                     const float* __restrict__ Wc, const float* __restrict__ bc) {
    __shared__ float qe[CP_TOK][KK2];
    int t0 = blockIdx.x * CP_TOK;
    int tid = threadIdx.x;
    for (int idx = tid; idx < CP_TOK * KK2; idx += blockDim.x) {
        int tt = idx / KK2, k = idx % KK2;
        qe[tt][k] = (k < HH) ? qt[(size_t)(t0 + tt) * HH + k]
                             : te[(size_t)(t0 + tt) * HH + k - HH];
    }
    __syncthreads();
    int n = tid;
    if (n >= NN) return;
    float acc[CP_TOK];
    #pragma unroll
    for (int tt = 0; tt < CP_TOK; tt++) acc[tt] = bc[n];
    for (int k = 0; k < KK2; k++) {
        float w = Wc[(size_t)k * NN + n];
        #pragma unroll
        for (int tt = 0; tt < CP_TOK; tt++) acc[tt] = fmaf(qe[tt][k], w, acc[tt]);
    }
    #pragma unroll
    for (int tt = 0; tt < CP_TOK; tt++) g_cp[(size_t)(t0 + tt) * NN + n] = acc[tt];
}

__global__ void k_m() {
    int b = blockIdx.x, n = threadIdx.x;
    if (n >= NN) return;
    float m = 0.f;
    for (int t = 0; t < TT; t++) {
        int bt = b * TT + t;
        float mg = g_mg[bt];
        m = g_cp[(size_t)bt * NN + n] * mg + m * (1.f - mg);
        g_M[(size_t)bt * NN + n] = m;
    }
}

#define GS_TT 16
__global__ void k_gsem() {
    __shared__ float Msh[GS_TT * NN];
    int b = blockIdx.x, t0 = blockIdx.y * GS_TT;
    int tid = threadIdx.x;
    for (int idx = tid; idx < GS_TT * NN; idx += blockDim.x) {
        int tt = idx / NN, j = idx % NN;
        Msh[tt * NN + j] = g_M[(size_t)(b * TT + t0 + tt) * NN + j];
    }
    __syncthreads();
    int i = tid;
    if (i >= NN) return;
    float acc[GS_TT];
    #pragma unroll
    for (int tt = 0; tt < GS_TT; tt++) acc[tt] = 0.f;
    const float* GT = g_graphT + (size_t)b * NN * NN;
    for (int j = 0; j < NN; j++) {
        float g = GT[(size_t)j * NN + i];
        #pragma unroll
        for (int tt = 0; tt < GS_TT; tt++) acc[tt] = fmaf(g, Msh[tt * NN + j], acc[tt]);
    }
    #pragma unroll
    for (int tt = 0; tt < GS_TT; tt++) {
        int bt = b * TT + t0 + tt;
        float gg = g_gg[bt];
        g_pg[(size_t)bt * NN + i] = g_cp[(size_t)bt * NN + i] * gg + acc[tt] * (1.f - gg);
    }
}

__global__ void k_cov(float* out_cov) {
    int bt = blockIdx.x;
    int b = bt / TT;
    int tid = threadIdx.x;
    float ps = g_ps[bt];
    float x = (tid < NN) ? g_pg[(size_t)bt * NN + tid] * ps : -1e30f;
    __shared__ float shm[32], shs[32];
    float mx = blk_reduce_max(x, shm);
    float e = (tid < NN) ? expf(x - mx) : 0.f;
    float s = blk_reduce_sum(e, shs);
    if (tid < NN) atomicAdd(&out_cov[b * NN + tid], e / s);
}

__global__ void k_scatter(const int* __restrict__ nidx, float* __restrict__ out) {
    int i = blockIdx.x * blockDim.x + threadIdx.x;
    if (i >= BT * NN) return;
    int bt = i / NN, n = i % NN;
    atomicAdd(&out[(size_t)bt * VV + nidx[n]], g_pg[i] * g_ps[bt]);
}

// ================= fp16 m16n8k16 GEMM =================
// out = (hq @ Wg + bg) * (1 - ps).  BM=512 (full M), BN=64, BK=32, 512 thr.
// A: fp16 cp.async, 3 stages, rows pitch 80B (conflict-free scalar frag loads).
// B: f32 LDG -> cvt -> swizzled half2 STS (kp ^ ((n>>3)&15)), 2 buffers.
// 16 warps = 8m x 2n, warp tile 64x32 (4 x m16, 4 x n8, 2 x k16 per k-block).

#define GH_BN 64
#define GH_KB (KK2 / 32)               // 64 k-blocks of 32
#define GH_AP 80                       // A row pitch bytes
#define GH_ASTG (512 * GH_AP)          // 40960
#define GH_BSTG (GH_BN * GH_AP)        // 5120
#define GH_SMEM (3 * GH_ASTG + 2 * GH_BSTG)  // 133120

__device__ __forceinline__ uint32_t smem_u32(const void* p) {
    uint32_t a;
    asm("{ .reg .u64 t; cvta.to.shared.u64 t, %1; cvt.u32.u64 %0, t; }" : "=r"(a) : "l"(p));
    return a;
}
__device__ __forceinline__ void cp16(uint32_t dst, const void* src) {
    asm volatile("cp.async.cg.shared.global [%0], [%1], 16;" :: "r"(dst), "l"(src));
}
__device__ __forceinline__ uint32_t lds32(uint32_t addr) {
    uint32_t v;
    asm volatile("ld.shared.u32 %0, [%1];" : "=r"(v) : "r"(addr));
    return v;
}
__device__ __forceinline__ void sts32(uint32_t addr, uint32_t v) {
    asm volatile("st.shared.u32 [%0], %1;" :: "r"(addr), "r"(v));
}

#define HMMA(c, a, b0v, b1v) \
    asm volatile("mma.sync.aligned.m16n8k16.row.col.f32.f16.f16.f32 " \
        "{%0,%1,%2,%3}, {%4,%5,%6,%7}, {%8,%9}, {%0,%1,%2,%3};" \
        : "+f"((c)[0]), "+f"((c)[1]), "+f"((c)[2]), "+f"((c)[3]) \
        : "r"((a)[0]), "r"((a)[1]), "r"((a)[2]), "r"((a)[3]), "r"(b0v), "r"(b1v))

__global__ __launch_bounds__(512, 1)
void k_gemm_h(const float* __restrict__ Wg, const float* __restrict__ bg,
              float* __restrict__ out) {
    extern __shared__ char smc[];
    const uint32_t sb = smem_u32(smc);
    const int tid = threadIdx.x, lane = tid & 31, wid = tid >> 5;
    const int n0 = blockIdx.x * GH_BN;
    const int g = lane >> 2, t = lane & 3;
    const int wm = (wid & 7) * 64, wn = (wid >> 3) * 32;

    float acc[4][4][4];
    #pragma unroll
    for (int mi = 0; mi < 4; mi++)
        #pragma unroll
        for (int nj = 0; nj < 4; nj++)
            #pragma unroll
            for (int q = 0; q < 4; q++) acc[mi][nj][q] = 0.f;

    // B staging indices (2 pairs per thread per k-block)
    const int bn0  = tid & 63;            // n for pair 0 (and 1)
    const int bkp0 = tid >> 6;            // kp 0..7
    const int bkp1 = bkp0 + 8;            // kp 8..15
    const int bs0  = (bn0 >> 3) & 15;     // swizzle

    // ---- A: cp.async one 32-k block into stage stg (4 chunks/thread) ----
    auto cpA = [&](int kb, int stg) {
        const uint32_t dstb = sb + (uint32_t)stg * GH_ASTG;
        const size_t srcb = (size_t)kb * 32;
        #pragma unroll
        for (int i = 0; i < 4; i++) {
            int idx = i * 512 + tid;       // 0..2047 : m = idx>>2, chunk = idx&3
            int m = idx >> 2, c = idx & 3;
            cp16(dstb + (uint32_t)(m * GH_AP + c * 16),
                 (const char*)(g_hqH + (size_t)m * KK2 + srcb) + c * 16);
        }
        asm volatile("cp.async.commit_group;" ::: "memory");
    };
    // ---- B: LDG 4 f32 (2 k-adjacent pairs) ----
    auto ldgB = [&](float (&rB)[4], int kb) {
        const int k0 = kb * 32;
        const int nn = n0 + bn0;
        const bool ok = nn < VV;
        const float* p0 = Wg + (size_t)(k0 + 2 * bkp0) * VV + (ok ? nn : 0);
        const float* p1 = Wg + (size_t)(k0 + 2 * bkp1) * VV + (ok ? nn : 0);
        rB[0] = ok ? p0[0] : 0.f;  rB[1] = ok ? p0[VV] : 0.f;
        rB[2] = ok ? p1[0] : 0.f;  rB[3] = ok ? p1[VV] : 0.f;
    };
    // ---- B: cvt + swizzled STS into buffer buf ----
    auto stsB = [&](const float (&rB)[4], int buf) {
        const uint32_t bb = sb + 3u * GH_ASTG + (uint32_t)buf * GH_BSTG
                          + (uint32_t)bn0 * GH_AP;
        __half2 h0 = __floats2half2_rn(rB[0], rB[1]);
        __half2 h1 = __floats2half2_rn(rB[2], rB[3]);
        sts32(bb + (uint32_t)((bkp0 ^ bs0) * 4), *(uint32_t*)&h0);
        sts32(bb + (uint32_t)((bkp1 ^ bs0) * 4), *(uint32_t*)&h1);
    };
    // ---- compute one 32-k block ----
    auto compute = [&](int kb) {
        const uint32_t As = sb + (uint32_t)(kb % 3) * GH_ASTG;
        const uint32_t Bs = sb + 3u * GH_ASTG + (uint32_t)(kb & 1) * GH_BSTG;
        #pragma unroll
        for (int ks = 0; ks < 2; ks++) {
            uint32_t a[4][4], b0[4], b1[4];
            #pragma unroll
            for (int mi = 0; mi < 4; mi++) {
                uint32_t base = As + (uint32_t)((wm + mi * 16 + g) * GH_AP + ks * 32 + t * 4);
                a[mi][0] = lds32(base);
                a[mi][1] = lds32(base + 8 * GH_AP);
                a[mi][2] = lds32(base + 16);
                a[mi][3] = lds32(base + 8 * GH_AP + 16);
            }
            #pragma unroll
            for (int nj = 0; nj < 4; nj++) {
                int nl = wn + nj * 8 + g;
                int s = (nl >> 3) & 15;
                uint32_t base = Bs + (uint32_t)nl * GH_AP;
                b0[nj] = lds32(base + (uint32_t)(((ks * 8 + t) ^ s) * 4));
                b1[nj] = lds32(base + (uint32_t)(((ks * 8 + t + 4) ^ s) * 4));
            }
            #pragma unroll
            for (int mi = 0; mi < 4; mi++)
                #pragma unroll
                for (int nj = 0; nj < 4; nj++)
                    HMMA(acc[mi][nj], a[mi], b0[nj], b1[nj]);
        }
    };

    // ---- prologue ----
    float rBa[4], rBb[4];
    cpA(0, 0);
    ldgB(rBa, 0);

    // ---- mainloop, unrolled by 2 (rBa = even kb, rBb = odd kb) ----
    #pragma unroll 1
    for (int kb = 0; kb < GH_KB; kb += 2) {
        // iter kb (even, B buf 0)
        stsB(rBa, 0);
        ldgB(rBb, kb + 1);
        cpA(kb + 1, (kb + 1) % 3);
        asm volatile("cp.async.wait_group 1;" ::: "memory");
        __syncthreads();
        compute(kb);

        // iter kb+1 (odd, B buf 1)
        stsB(rBb, 1);
        if (kb + 2 < GH_KB) {
            ldgB(rBa, kb + 2);
            cpA(kb + 2, (kb + 2) % 3);
            asm volatile("cp.async.wait_group 1;" ::: "memory");
        } else {
            asm volatile("cp.async.wait_group 0;" ::: "memory");
        }
        __syncthreads();
        compute(kb + 1);
    }

    // ---- epilogue: out = (acc + bg) * (1 - ps) ----
    #pragma unroll
    for (int mi = 0; mi < 4; mi++) {
        int m = wm + mi * 16 + g;
        float s0 = 1.f - g_ps[m];
        float s1 = 1.f - g_ps[m + 8];
        #pragma unroll
        for (int nj = 0; nj < 4; nj++) {
            int n = n0 + wn + nj * 8 + t * 2;
            if (n < VV) {
                float bgv = bg[n];
                out[(size_t)m * VV + n]       = (acc[mi][nj][0] + bgv) * s0;
                out[(size_t)(m + 8) * VV + n] = (acc[mi][nj][2] + bgv) * s1;
            }
            if (n + 1 < VV) {
                float bgv = bg[n + 1];
                out[(size_t)m * VV + n + 1]       = (acc[mi][nj][1] + bgv) * s0;
                out[(size_t)(m + 8) * VV + n + 1] = (acc[mi][nj][3] + bgv) * s1;
            }
        }
    }
}

// ---------------- launch ----------------
extern "C" void kernel_launch(void* const* d_in, const int* in_sizes, int n_in,
                              void* d_out, int out_size) {
    const float* hs   = (const float*)d_in[0];
    const float* qt   = (const float*)d_in[1];
    const float* te   = (const float*)d_in[2];
    const int*   edges= (const int*)  d_in[3];
    const int*   nidx = (const int*)  d_in[4];
    const float* Wg   = (const float*)d_in[5];
    const float* bg   = (const float*)d_in[6];
    const float* Wh   = (const float*)d_in[7];
    const float* Ws   = (const float*)d_in[8];
    const float* Wx   = (const float*)d_in[9];
    const float* bx   = (const float*)d_in[10];
    const float* Wps  = (const float*)d_in[11];
    const float* bps  = (const float*)d_in[12];
    const float* Wc   = (const float*)d_in[13];
    const float* bc   = (const float*)d_in[14];
    const float* Wgg  = (const float*)d_in[15];
    const float* bgg  = (const float*)d_in[16];
    const float* Wmg  = (const float*)d_in[17];
    const float* bmg  = (const float*)d_in[18];

    float* out    = (float*)d_out;
    float* outCov = out + (size_t)BT * VV;
    float* outPs  = outCov + BB * NN;

    cudaFuncSetAttribute(k_gemm_h, cudaFuncAttributeMaxDynamicSharedMemorySize, GH_SMEM);

    k_zero<<<(BB*NN*NN + 255) / 256, 256>>>(outCov);
    k_vec<<<(3 * HH * 32 + 255) / 256, 256>>>(Wh, Ws, Wx, Wps);
    k_tok<<<BT, 256>>>(hs, qt, te, bx, Wps, bps, Wgg, bgg, Wmg, bmg, outPs);
    k_edges<<<(BB*EE + 255) / 256, 256>>>(edges);
    k_cp<<<BT / CP_TOK, 320>>>(qt, te, Wc, bc);
    k_m<<<BB, 320>>>();
    k_gsem<<<dim3(BB, TT / GS_TT), 320>>>();
    k_cov<<<BT, 320>>>(outCov);
    k_gemm_h<<<(VV + GH_BN - 1) / GH_BN, 512, GH_SMEM>>>(Wg, bg, out);
    k_scatter<<<(BT*NN + 255) / 256, 256>>>(nidx, out);
}